// round 13
// baseline (speedup 1.0000x reference)
#include <cuda_runtime.h>
#include <cuda_fp16.h>
#include <cooperative_groups.h>
#include <math.h>

namespace cg = cooperative_groups;

#define N_NODES 50000
#define N_EDGES 1600000
#define CH 128
#define CH4 (CH / 4)
#define HEADS 4
#define NEG_SLOPE 0.2f
#define N_ROOTS 64
#define ACT_MAX 4096           // bound on |A1| (realistic ~2100)
#define CAP 128                // slots per active node
#define NMASK ((N_NODES + 31) / 32 + 1)
#define EPT 16                 // edges per thread in the coop sweep
#define NSWEEP (N_EDGES / EPT) // 100000 threads
#define COOP_BLOCKS ((NSWEEP + 255) / 256)   // 391

#define GM 128                 // gemm rows per block
#define SX 136                 // gemm smem stride (halves)
#define GEMM_SMEM ((GM * SX + CH * SX) * 2)

// ---------------- persistent device scratch ----------------
__device__ uint4    g_hh[(size_t)N_NODES * 16];      // h as fp16 (128 halves/node)
__device__ float4   g_feat4[(size_t)N_NODES * CH4];  // layer-1 output (fp32)
__device__ float    g_as[N_NODES * HEADS];
__device__ float    g_ad[N_NODES * HEADS];
__device__ __half   g_W16[2][CH * CH];               // W1,W2 fp16, transposed (n-major)
__device__ unsigned g_rootmask[NMASK];
__device__ unsigned g_actmask[NMASK];
__device__ int      g_dense[N_NODES];                // 0=inactive, -1=claiming, else dense+1
__device__ int      g_active[ACT_MAX];
__device__ int      g_cnt[ACT_MAX];
__device__ int      g_slots[(size_t)ACT_MAX * CAP];
__device__ int      g_nactive;

// ---------------- W fp16 transpose conversion (once per call, side stream) ----------------
__global__ void wconvert_kernel(const float* __restrict__ W1,
                                const float* __restrict__ W2) {
    int idx = blockIdx.x * blockDim.x + threadIdx.x;
    if (idx < CH * CH) {
        int n = idx >> 7, k = idx & 127;
        g_W16[0][idx] = __float2half(W1[k * CH + n]);
        g_W16[1][idx] = __float2half(W2[k * CH + n]);
    }
}

__device__ __forceinline__ void claim_active(int node) {
    if (atomicCAS(&g_dense[node], 0, -1) == 0) {
        int p = atomicAdd(&g_nactive, 1);
        if (p < ACT_MAX) {
            g_active[p] = node;
            g_slots[(size_t)p * CAP] = node;   // self loop in slot 0
            g_cnt[p] = 1;
            atomicOr(&g_actmask[node >> 5], 1u << (node & 31));
            g_dense[node] = p + 1;
        }
    }
}

// ---------------- cooperative prep: zero -> mark -> discover -> scatter ----------------
// dst values stay register-resident across discover/scatter (one dst sweep total).
__global__ __launch_bounds__(256, 4) void prep_coop_kernel(
        const int* __restrict__ ei,
        const int* __restrict__ roots) {
    cg::grid_group grid = cg::this_grid();
    int t = blockIdx.x * blockDim.x + threadIdx.x;
    int nt = gridDim.x * blockDim.x;

    // phase 0: zero state
    for (int i = t; i < N_NODES / 4; i += nt) ((int4*)g_dense)[i] = make_int4(0, 0, 0, 0);
    for (int i = t; i < NMASK; i += nt) { g_rootmask[i] = 0u; g_actmask[i] = 0u; }
    for (int i = t; i < ACT_MAX; i += nt) g_cnt[i] = 0;
    if (t == 0) g_nactive = 0;
    grid.sync();

    // phase 1: mark roots
    if (t < N_ROOTS) {
        int r = roots[t];
        atomicOr(&g_rootmask[r >> 5], 1u << (r & 31));
        claim_active(r);
    }
    grid.sync();

    // phase 2: discover (load dst into registers, keep for phase 3)
    int4 d[EPT / 4];
    bool havework = (t < NSWEEP);
    if (havework) {
        const int4* dst4 = (const int4*)(ei + N_EDGES);
#pragma unroll
        for (int q = 0; q < EPT / 4; q++) d[q] = dst4[(EPT / 4) * t + q];
        const int* dv = (const int*)d;
#pragma unroll
        for (int k = 0; k < EPT; k++) {
            int dst = dv[k];
            if ((g_rootmask[dst >> 5] >> (dst & 31)) & 1u) {
                claim_active(ei[EPT * t + k]);
            }
        }
    }
    grid.sync();

    // phase 3: scatter using register-resident dst
    if (havework) {
        const int* dv = (const int*)d;
#pragma unroll
        for (int k = 0; k < EPT; k++) {
            int dst = dv[k];
            if ((g_actmask[dst >> 5] >> (dst & 31)) & 1u) {
                int di = g_dense[dst];
                if (di > 0) {
                    int src = ei[EPT * t + k];
                    int pos = atomicAdd(&g_cnt[di - 1], 1);
                    if (pos < CAP) g_slots[(size_t)(di - 1) * CAP + pos] = src;
                }
            }
        }
    }
}

// ---------------- HMMA GEMM + fused alpha logits, fp16 h output ----------------
__global__ __launch_bounds__(256) void gemm_alpha_mma(
        const float* __restrict__ Xin,
        const float* __restrict__ asrc,
        const float* __restrict__ adst,
        int widx, int use_act) {
    extern __shared__ __half smh[];
    __half* xs = smh;               // [GM][SX]
    __half* Wt = smh + GM * SX;     // [128 n][SX k]

    int row0 = blockIdx.x * GM;
    int nact = use_act ? g_nactive : N_NODES;
    if (row0 >= nact) return;

    int tid = threadIdx.x;
    int lane = tid & 31;
    int w = tid >> 5;
    const float* Xsrc = use_act ? (const float*)g_feat4 : Xin;
    const uint4* Wg = (const uint4*)g_W16[widx];

#pragma unroll
    for (int i = 0; i < 8; i++) {
        int idx8 = tid + 256 * i;
        int n  = idx8 >> 4;
        int k0 = (idx8 & 15) * 8;
        *(uint4*)(Wt + n * SX + k0) = Wg[idx8];
    }
#pragma unroll
    for (int i = 0; i < 16; i++) {
        int idx = tid + 256 * i;
        int r = idx >> 5, k4 = idx & 31;
        int pos = row0 + r;
        float4 v = make_float4(0.f, 0.f, 0.f, 0.f);
        if (pos < nact) {
            int node = use_act ? g_active[pos] : pos;
            v = *(const float4*)(Xsrc + (size_t)node * CH + 4 * k4);
            if (use_act) {
                v.x = fmaxf(v.x, 0.f); v.y = fmaxf(v.y, 0.f);
                v.z = fmaxf(v.z, 0.f); v.w = fmaxf(v.w, 0.f);
            }
        }
        *(__half2*)(xs + r * SX + 4 * k4)     = __floats2half2_rn(v.x, v.y);
        *(__half2*)(xs + r * SX + 4 * k4 + 2) = __floats2half2_rn(v.z, v.w);
    }
    __syncthreads();

    int qr = lane >> 2;
    int qc = (lane & 3) * 2;
    int wrow = w * 16;

    float acc[16][4];
#pragma unroll
    for (int nt = 0; nt < 16; nt++) {
        acc[nt][0] = acc[nt][1] = acc[nt][2] = acc[nt][3] = 0.f;
    }

#pragma unroll
    for (int kc = 0; kc < CH; kc += 16) {
        unsigned a0 = *(const unsigned*)(xs + (wrow + qr) * SX + kc + qc);
        unsigned a1 = *(const unsigned*)(xs + (wrow + qr + 8) * SX + kc + qc);
        unsigned a2 = *(const unsigned*)(xs + (wrow + qr) * SX + kc + qc + 8);
        unsigned a3 = *(const unsigned*)(xs + (wrow + qr + 8) * SX + kc + qc + 8);
#pragma unroll
        for (int nt = 0; nt < 16; nt++) {
            int n = nt * 8 + qr;
            unsigned b0 = *(const unsigned*)(Wt + n * SX + kc + qc);
            unsigned b1 = *(const unsigned*)(Wt + n * SX + kc + qc + 8);
            asm volatile(
                "mma.sync.aligned.m16n8k16.row.col.f32.f16.f16.f32 "
                "{%0,%1,%2,%3}, {%4,%5,%6,%7}, {%8,%9}, {%0,%1,%2,%3};"
                : "+f"(acc[nt][0]), "+f"(acc[nt][1]), "+f"(acc[nt][2]), "+f"(acc[nt][3])
                : "r"(a0), "r"(a1), "r"(a2), "r"(a3), "r"(b0), "r"(b1));
        }
    }

    int pos0 = row0 + wrow + qr;
    int pos1 = pos0 + 8;
    int ok0 = pos0 < nact, ok1 = pos1 < nact;
    int gr0 = ok0 ? (use_act ? g_active[pos0] : pos0) : 0;
    int gr1 = ok1 ? (use_act ? g_active[pos1] : pos1) : 0;

    float s0[HEADS], d0[HEADS], s1[HEADS], d1[HEADS];
#pragma unroll
    for (int h = 0; h < HEADS; h++) { s0[h] = d0[h] = s1[h] = d1[h] = 0.f; }

#pragma unroll
    for (int nt = 0; nt < 16; nt++) {
        float2 a_s = *(const float2*)(asrc + nt * 8 + qc);
        float2 a_d = *(const float2*)(adst + nt * 8 + qc);
        int h = nt >> 2;
        s0[h] += acc[nt][0] * a_s.x + acc[nt][1] * a_s.y;
        d0[h] += acc[nt][0] * a_d.x + acc[nt][1] * a_d.y;
        s1[h] += acc[nt][2] * a_s.x + acc[nt][3] * a_s.y;
        d1[h] += acc[nt][2] * a_d.x + acc[nt][3] * a_d.y;
        if (ok0) {
            __half2 p = __floats2half2_rn(acc[nt][0], acc[nt][1]);
            ((unsigned*)g_hh)[(size_t)gr0 * 64 + nt * 4 + (lane & 3)] = *(unsigned*)&p;
        }
        if (ok1) {
            __half2 p = __floats2half2_rn(acc[nt][2], acc[nt][3]);
            ((unsigned*)g_hh)[(size_t)gr1 * 64 + nt * 4 + (lane & 3)] = *(unsigned*)&p;
        }
    }
#pragma unroll
    for (int h = 0; h < HEADS; h++) {
        s0[h] += __shfl_xor_sync(0xffffffffu, s0[h], 1);
        s0[h] += __shfl_xor_sync(0xffffffffu, s0[h], 2);
        d0[h] += __shfl_xor_sync(0xffffffffu, d0[h], 1);
        d0[h] += __shfl_xor_sync(0xffffffffu, d0[h], 2);
        s1[h] += __shfl_xor_sync(0xffffffffu, s1[h], 1);
        s1[h] += __shfl_xor_sync(0xffffffffu, s1[h], 2);
        d1[h] += __shfl_xor_sync(0xffffffffu, d1[h], 1);
        d1[h] += __shfl_xor_sync(0xffffffffu, d1[h], 2);
    }
    if ((lane & 3) == 0) {
#pragma unroll
        for (int h = 0; h < HEADS; h++) {
            if (ok0) { g_as[gr0 * HEADS + h] = s0[h]; g_ad[gr0 * HEADS + h] = d0[h]; }
            if (ok1) { g_as[gr1 * HEADS + h] = s1[h]; g_ad[gr1 * HEADS + h] = d1[h]; }
        }
    }
}

// ---------------- aggregation core: warp per dst node over a slot bucket ----------------
__device__ __forceinline__ void aggregate_node(int node, int di, int lane,
                                               const float* __restrict__ bias,
                                               float* __restrict__ outp) {
    int g = lane >> 3;
    int j = lane & 7;
    int head = j >> 1;

    float ad = g_ad[node * HEADS + head];
    const int* slots = g_slots + (size_t)di * CAP;
    int cnt = g_cnt[di];
    if (cnt > CAP) cnt = CAP;

    float dsum = 0.0f;
    float acc[16];
#pragma unroll
    for (int i = 0; i < 16; i++) acc[i] = 0.0f;

    int e = g;
    float as_c = 0.0f;
    uint4 ha_c = make_uint4(0, 0, 0, 0), hb_c = make_uint4(0, 0, 0, 0);
    if (e < cnt) {
        int s = slots[e];
        as_c = g_as[s * HEADS + head];
        ha_c = g_hh[(size_t)s * 16 + 2 * j];
        hb_c = g_hh[(size_t)s * 16 + 2 * j + 1];
    }
    while (e < cnt) {
        int e_n = e + 4;
        float as_n = 0.0f;
        uint4 ha_n = make_uint4(0, 0, 0, 0), hb_n = make_uint4(0, 0, 0, 0);
        if (e_n < cnt) {
            int s_n = slots[e_n];
            as_n = g_as[s_n * HEADS + head];
            ha_n = g_hh[(size_t)s_n * 16 + 2 * j];
            hb_n = g_hh[(size_t)s_n * 16 + 2 * j + 1];
        }

        float v = as_c + ad;
        v = fmaxf(v, NEG_SLOPE * v);
        float w = __expf(v);
        float2 f;
        f = __half22float2(*(__half2*)&ha_c.x); acc[0]  = fmaf(w, f.x, acc[0]);  acc[1]  = fmaf(w, f.y, acc[1]);
        f = __half22float2(*(__half2*)&ha_c.y); acc[2]  = fmaf(w, f.x, acc[2]);  acc[3]  = fmaf(w, f.y, acc[3]);
        f = __half22float2(*(__half2*)&ha_c.z); acc[4]  = fmaf(w, f.x, acc[4]);  acc[5]  = fmaf(w, f.y, acc[5]);
        f = __half22float2(*(__half2*)&ha_c.w); acc[6]  = fmaf(w, f.x, acc[6]);  acc[7]  = fmaf(w, f.y, acc[7]);
        f = __half22float2(*(__half2*)&hb_c.x); acc[8]  = fmaf(w, f.x, acc[8]);  acc[9]  = fmaf(w, f.y, acc[9]);
        f = __half22float2(*(__half2*)&hb_c.y); acc[10] = fmaf(w, f.x, acc[10]); acc[11] = fmaf(w, f.y, acc[11]);
        f = __half22float2(*(__half2*)&hb_c.z); acc[12] = fmaf(w, f.x, acc[12]); acc[13] = fmaf(w, f.y, acc[13]);
        f = __half22float2(*(__half2*)&hb_c.w); acc[14] = fmaf(w, f.x, acc[14]); acc[15] = fmaf(w, f.y, acc[15]);
        dsum += w;

        e = e_n; as_c = as_n; ha_c = ha_n; hb_c = hb_n;
    }

    dsum += __shfl_xor_sync(0xffffffffu, dsum, 8);
    dsum += __shfl_xor_sync(0xffffffffu, dsum, 16);
#pragma unroll
    for (int i = 0; i < 16; i++) {
        acc[i] += __shfl_xor_sync(0xffffffffu, acc[i], 8);
        acc[i] += __shfl_xor_sync(0xffffffffu, acc[i], 16);
    }
    float inv = 1.0f / (dsum + 1e-16f);

    int c0 = 16 * j + 4 * g;
    float4 o;
    o.x = acc[4 * g + 0] * inv + bias[c0 + 0];
    o.y = acc[4 * g + 1] * inv + bias[c0 + 1];
    o.z = acc[4 * g + 2] * inv + bias[c0 + 2];
    o.w = acc[4 * g + 3] * inv + bias[c0 + 3];
    *(float4*)(outp + c0) = o;
}

__global__ void aggregate1_kernel(const float* __restrict__ bias) {
    int idx = (blockIdx.x * blockDim.x + threadIdx.x) >> 5;
    int lane = threadIdx.x & 31;
    if (idx >= g_nactive) return;
    int node = g_active[idx];
    aggregate_node(node, idx, lane, bias, (float*)g_feat4 + (size_t)node * CH);
}

__global__ void aggregate2_kernel(const float* __restrict__ bias,
                                  const int* __restrict__ roots,
                                  float* __restrict__ out) {
    int b = (blockIdx.x * blockDim.x + threadIdx.x) >> 5;
    int lane = threadIdx.x & 31;
    if (b >= N_ROOTS) return;
    int node = roots[b];
    int di = g_dense[node] - 1;
    aggregate_node(node, di, lane, bias, out + (size_t)b * CH);
}

// ---------------- launch ----------------
extern "C" void kernel_launch(void* const* d_in, const int* in_sizes, int n_in,
                              void* d_out, int out_size) {
    const float* x     = (const float*)d_in[0];
    const int*   ei    = (const int*)d_in[1];
    const int*   roots = (const int*)d_in[2];
    const float* W1    = (const float*)d_in[3];
    const float* a1s   = (const float*)d_in[4];
    const float* a1d   = (const float*)d_in[5];
    const float* b1    = (const float*)d_in[6];
    const float* W2    = (const float*)d_in[7];
    const float* a2s   = (const float*)d_in[8];
    const float* a2d   = (const float*)d_in[9];
    const float* b2    = (const float*)d_in[10];
    float*       out   = (float*)d_out;

    static cudaStream_t s2 = 0;
    static cudaEvent_t evFork = 0, evJoin = 0;
    if (s2 == 0) {
        cudaStreamCreate(&s2);
        cudaEventCreateWithFlags(&evFork, cudaEventDisableTiming);
        cudaEventCreateWithFlags(&evJoin, cudaEventDisableTiming);
        cudaFuncSetAttribute(gemm_alpha_mma,
                             cudaFuncAttributeMaxDynamicSharedMemorySize, GEMM_SMEM);
    }

    const int T = 256;
    int nb_wcv   = (CH * CH + T - 1) / T;
    int nb_gemm1 = (N_NODES + GM - 1) / GM;
    int nb_gemm2 = (ACT_MAX + GM - 1) / GM;
    int nb_agg1  = (ACT_MAX * 32 + T - 1) / T;
    int nb_agg2  = (N_ROOTS * 32 + T - 1) / T;

    // side stream: W conversion + full-graph layer-1 GEMM
    cudaEventRecord(evFork, 0);
    cudaStreamWaitEvent(s2, evFork, 0);
    wconvert_kernel<<<nb_wcv, T, 0, s2>>>(W1, W2);
    gemm_alpha_mma<<<nb_gemm1, T, GEMM_SMEM, s2>>>(x, a1s, a1d, 0, 0);
    cudaEventRecord(evJoin, s2);

    // main stream: single cooperative prep kernel (zero+mark+discover+scatter)
    {
        void* args[] = { (void*)&ei, (void*)&roots };
        cudaLaunchCooperativeKernel((void*)prep_coop_kernel,
                                    dim3(COOP_BLOCKS), dim3(T), args, 0, 0);
    }

    cudaStreamWaitEvent(0, evJoin, 0);
    aggregate1_kernel<<<nb_agg1, T>>>(b1);
    gemm_alpha_mma<<<nb_gemm2, T, GEMM_SMEM>>>(x, a2s, a2d, 1, 1);
    aggregate2_kernel<<<nb_agg2, T>>>(b2, roots, out);
}

// round 14
// speedup vs baseline: 1.3327x; 1.3327x over previous
#include <cuda_runtime.h>
#include <cuda_fp16.h>
#include <math.h>

#define N_NODES 50000
#define N_EDGES 1600000
#define CH 128
#define CH4 (CH / 4)
#define HEADS 4
#define NEG_SLOPE 0.2f
#define N_ROOTS 64
#define ACT_MAX 4096           // bound on |A1| (realistic ~2100)
#define CAP 128                // slots per active node
#define NMASK ((N_NODES + 31) / 32 + 1)

#define GM 128                 // gemm rows per block
#define SX 136                 // gemm smem stride (halves)
#define GEMM_SMEM ((GM * SX + CH * SX) * 2)

// ---------------- persistent device scratch ----------------
__device__ uint4    g_hh[(size_t)N_NODES * 16];      // h as fp16 (128 halves/node)
__device__ float4   g_feat4[(size_t)N_NODES * CH4];  // layer-1 output (fp32)
__device__ float    g_as[N_NODES * HEADS];
__device__ float    g_ad[N_NODES * HEADS];
__device__ __half   g_W16[2][CH * CH];               // W1,W2 fp16, transposed (n-major)
__device__ unsigned g_rootmask[NMASK];               // 6.25 KB, L1-resident
__device__ unsigned g_actmask[NMASK];
__device__ int      g_dense[N_NODES];                // 0=inactive, -1=claiming, else dense+1
__device__ int      g_active[ACT_MAX];
__device__ int      g_cnt[ACT_MAX];
__device__ int      g_slots[(size_t)ACT_MAX * CAP];
__device__ int      g_nactive;

// ---------------- W fp16 transpose conversion (once per call, side stream) ----------------
__global__ void wconvert_kernel(const float* __restrict__ W1,
                                const float* __restrict__ W2) {
    int idx = blockIdx.x * blockDim.x + threadIdx.x;
    if (idx < CH * CH) {
        int n = idx >> 7, k = idx & 127;
        g_W16[0][idx] = __float2half(W1[k * CH + n]);
        g_W16[1][idx] = __float2half(W2[k * CH + n]);
    }
}

// ---------------- setup ----------------
__global__ void zero_kernel() {
    int i = blockIdx.x * blockDim.x + threadIdx.x;
    if (i < N_NODES / 4) ((int4*)g_dense)[i] = make_int4(0, 0, 0, 0);
    if (i < NMASK) { g_rootmask[i] = 0u; g_actmask[i] = 0u; }
    if (i < ACT_MAX) g_cnt[i] = 0;
    if (i == 0) g_nactive = 0;
}

__device__ __forceinline__ void claim_active(int node) {
    if (atomicCAS(&g_dense[node], 0, -1) == 0) {
        int p = atomicAdd(&g_nactive, 1);
        if (p < ACT_MAX) {
            g_active[p] = node;
            g_slots[(size_t)p * CAP] = node;   // self loop in slot 0
            g_cnt[p] = 1;
            atomicOr(&g_actmask[node >> 5], 1u << (node & 31));
            g_dense[node] = p + 1;
        }
    }
}

__global__ void mark_roots_kernel(const int* __restrict__ roots) {
    int t = threadIdx.x;
    if (t < N_ROOTS) {
        int r = roots[t];
        atomicOr(&g_rootmask[r >> 5], 1u << (r & 31));
        claim_active(r);
    }
}

// A1 = roots U in-neighbors(roots). 8 edges/thread, bitmask probe.
__global__ void discover_kernel(const int* __restrict__ ei) {
    int e8 = blockIdx.x * blockDim.x + threadIdx.x;
    if (e8 >= N_EDGES / 8) return;
    const int4* dst4 = (const int4*)(ei + N_EDGES);
    int4 d0 = dst4[2 * e8];
    int4 d1 = dst4[2 * e8 + 1];
    int dv[8] = {d0.x, d0.y, d0.z, d0.w, d1.x, d1.y, d1.z, d1.w};
#pragma unroll
    for (int k = 0; k < 8; k++) {
        int dst = dv[k];
        if ((g_rootmask[dst >> 5] >> (dst & 31)) & 1u) {
            claim_active(ei[8 * e8 + k]);
        }
    }
}

// scatter edges into active-dst slot buckets. 8 edges/thread, bitmask prefilter.
__global__ void scatter_kernel(const int* __restrict__ ei) {
    int e8 = blockIdx.x * blockDim.x + threadIdx.x;
    if (e8 >= N_EDGES / 8) return;
    const int4* dst4 = (const int4*)(ei + N_EDGES);
    int4 d0 = dst4[2 * e8];
    int4 d1 = dst4[2 * e8 + 1];
    int dv[8] = {d0.x, d0.y, d0.z, d0.w, d1.x, d1.y, d1.z, d1.w};
#pragma unroll
    for (int k = 0; k < 8; k++) {
        int dst = dv[k];
        if ((g_actmask[dst >> 5] >> (dst & 31)) & 1u) {
            int di = g_dense[dst];
            if (di > 0) {
                int src = ei[8 * e8 + k];
                int pos = atomicAdd(&g_cnt[di - 1], 1);
                if (pos < CAP) g_slots[(size_t)(di - 1) * CAP + pos] = src;
            }
        }
    }
}

// ---------------- HMMA GEMM + fused alpha logits, fp16 h output ----------------
__global__ __launch_bounds__(256) void gemm_alpha_mma(
        const float* __restrict__ Xin,
        const float* __restrict__ asrc,
        const float* __restrict__ adst,
        int widx, int use_act) {
    extern __shared__ __half smh[];
    __half* xs = smh;               // [GM][SX]
    __half* Wt = smh + GM * SX;     // [128 n][SX k]

    int row0 = blockIdx.x * GM;
    int nact = use_act ? g_nactive : N_NODES;
    if (row0 >= nact) return;

    int tid = threadIdx.x;
    int lane = tid & 31;
    int w = tid >> 5;
    const float* Xsrc = use_act ? (const float*)g_feat4 : Xin;
    const uint4* Wg = (const uint4*)g_W16[widx];

    // stage W: 2048 uint4 (pre-converted fp16, vectorized)
#pragma unroll
    for (int i = 0; i < 8; i++) {
        int idx8 = tid + 256 * i;
        int n  = idx8 >> 4;
        int k0 = (idx8 & 15) * 8;
        *(uint4*)(Wt + n * SX + k0) = Wg[idx8];
    }
    // stage x rows as fp16
#pragma unroll
    for (int i = 0; i < 16; i++) {
        int idx = tid + 256 * i;
        int r = idx >> 5, k4 = idx & 31;
        int pos = row0 + r;
        float4 v = make_float4(0.f, 0.f, 0.f, 0.f);
        if (pos < nact) {
            int node = use_act ? g_active[pos] : pos;
            v = *(const float4*)(Xsrc + (size_t)node * CH + 4 * k4);
            if (use_act) {
                v.x = fmaxf(v.x, 0.f); v.y = fmaxf(v.y, 0.f);
                v.z = fmaxf(v.z, 0.f); v.w = fmaxf(v.w, 0.f);
            }
        }
        *(__half2*)(xs + r * SX + 4 * k4)     = __floats2half2_rn(v.x, v.y);
        *(__half2*)(xs + r * SX + 4 * k4 + 2) = __floats2half2_rn(v.z, v.w);
    }
    __syncthreads();

    int qr = lane >> 2;
    int qc = (lane & 3) * 2;
    int wrow = w * 16;

    float acc[16][4];
#pragma unroll
    for (int nt = 0; nt < 16; nt++) {
        acc[nt][0] = acc[nt][1] = acc[nt][2] = acc[nt][3] = 0.f;
    }

#pragma unroll
    for (int kc = 0; kc < CH; kc += 16) {
        unsigned a0 = *(const unsigned*)(xs + (wrow + qr) * SX + kc + qc);
        unsigned a1 = *(const unsigned*)(xs + (wrow + qr + 8) * SX + kc + qc);
        unsigned a2 = *(const unsigned*)(xs + (wrow + qr) * SX + kc + qc + 8);
        unsigned a3 = *(const unsigned*)(xs + (wrow + qr + 8) * SX + kc + qc + 8);
#pragma unroll
        for (int nt = 0; nt < 16; nt++) {
            int n = nt * 8 + qr;
            unsigned b0 = *(const unsigned*)(Wt + n * SX + kc + qc);
            unsigned b1 = *(const unsigned*)(Wt + n * SX + kc + qc + 8);
            asm volatile(
                "mma.sync.aligned.m16n8k16.row.col.f32.f16.f16.f32 "
                "{%0,%1,%2,%3}, {%4,%5,%6,%7}, {%8,%9}, {%0,%1,%2,%3};"
                : "+f"(acc[nt][0]), "+f"(acc[nt][1]), "+f"(acc[nt][2]), "+f"(acc[nt][3])
                : "r"(a0), "r"(a1), "r"(a2), "r"(a3), "r"(b0), "r"(b1));
        }
    }

    int pos0 = row0 + wrow + qr;
    int pos1 = pos0 + 8;
    int ok0 = pos0 < nact, ok1 = pos1 < nact;
    int gr0 = ok0 ? (use_act ? g_active[pos0] : pos0) : 0;
    int gr1 = ok1 ? (use_act ? g_active[pos1] : pos1) : 0;

    float s0[HEADS], d0[HEADS], s1[HEADS], d1[HEADS];
#pragma unroll
    for (int h = 0; h < HEADS; h++) { s0[h] = d0[h] = s1[h] = d1[h] = 0.f; }

#pragma unroll
    for (int nt = 0; nt < 16; nt++) {
        float2 a_s = *(const float2*)(asrc + nt * 8 + qc);
        float2 a_d = *(const float2*)(adst + nt * 8 + qc);
        int h = nt >> 2;
        s0[h] += acc[nt][0] * a_s.x + acc[nt][1] * a_s.y;
        d0[h] += acc[nt][0] * a_d.x + acc[nt][1] * a_d.y;
        s1[h] += acc[nt][2] * a_s.x + acc[nt][3] * a_s.y;
        d1[h] += acc[nt][2] * a_d.x + acc[nt][3] * a_d.y;
        if (ok0) {
            __half2 p = __floats2half2_rn(acc[nt][0], acc[nt][1]);
            ((unsigned*)g_hh)[(size_t)gr0 * 64 + nt * 4 + (lane & 3)] = *(unsigned*)&p;
        }
        if (ok1) {
            __half2 p = __floats2half2_rn(acc[nt][2], acc[nt][3]);
            ((unsigned*)g_hh)[(size_t)gr1 * 64 + nt * 4 + (lane & 3)] = *(unsigned*)&p;
        }
    }
#pragma unroll
    for (int h = 0; h < HEADS; h++) {
        s0[h] += __shfl_xor_sync(0xffffffffu, s0[h], 1);
        s0[h] += __shfl_xor_sync(0xffffffffu, s0[h], 2);
        d0[h] += __shfl_xor_sync(0xffffffffu, d0[h], 1);
        d0[h] += __shfl_xor_sync(0xffffffffu, d0[h], 2);
        s1[h] += __shfl_xor_sync(0xffffffffu, s1[h], 1);
        s1[h] += __shfl_xor_sync(0xffffffffu, s1[h], 2);
        d1[h] += __shfl_xor_sync(0xffffffffu, d1[h], 1);
        d1[h] += __shfl_xor_sync(0xffffffffu, d1[h], 2);
    }
    if ((lane & 3) == 0) {
#pragma unroll
        for (int h = 0; h < HEADS; h++) {
            if (ok0) { g_as[gr0 * HEADS + h] = s0[h]; g_ad[gr0 * HEADS + h] = d0[h]; }
            if (ok1) { g_as[gr1 * HEADS + h] = s1[h]; g_ad[gr1 * HEADS + h] = d1[h]; }
        }
    }
}

// ---------------- aggregation core: warp/node, depth-2 pipelined (8 chains in flight) ----------------
struct EdgeState { float as; uint4 ha, hb; };

__device__ __forceinline__ void load_edge(const int* __restrict__ slots, int e,
                                          int head, int j, EdgeState& st) {
    int s = slots[e];
    st.as = g_as[s * HEADS + head];
    st.ha = g_hh[(size_t)s * 16 + 2 * j];
    st.hb = g_hh[(size_t)s * 16 + 2 * j + 1];
}

__device__ __forceinline__ void aggregate_node(int node, int di, int lane,
                                               const float* __restrict__ bias,
                                               float* __restrict__ outp) {
    int g = lane >> 3;
    int j = lane & 7;
    int head = j >> 1;

    float ad = g_ad[node * HEADS + head];
    const int* slots = g_slots + (size_t)di * CAP;
    int cnt = g_cnt[di];
    if (cnt > CAP) cnt = CAP;

    float dsum = 0.0f;
    float acc[16];
#pragma unroll
    for (int i = 0; i < 16; i++) acc[i] = 0.0f;

    EdgeState a = {}, b = {};
    int e = g;
    if (e < cnt)     load_edge(slots, e, head, j, a);
    if (e + 4 < cnt) load_edge(slots, e + 4, head, j, b);

    while (e < cnt) {
        EdgeState n = {};
        if (e + 8 < cnt) load_edge(slots, e + 8, head, j, n);

        float v = a.as + ad;
        v = fmaxf(v, NEG_SLOPE * v);
        float w = __expf(v);
        float2 f;
        f = __half22float2(*(__half2*)&a.ha.x); acc[0]  = fmaf(w, f.x, acc[0]);  acc[1]  = fmaf(w, f.y, acc[1]);
        f = __half22float2(*(__half2*)&a.ha.y); acc[2]  = fmaf(w, f.x, acc[2]);  acc[3]  = fmaf(w, f.y, acc[3]);
        f = __half22float2(*(__half2*)&a.ha.z); acc[4]  = fmaf(w, f.x, acc[4]);  acc[5]  = fmaf(w, f.y, acc[5]);
        f = __half22float2(*(__half2*)&a.ha.w); acc[6]  = fmaf(w, f.x, acc[6]);  acc[7]  = fmaf(w, f.y, acc[7]);
        f = __half22float2(*(__half2*)&a.hb.x); acc[8]  = fmaf(w, f.x, acc[8]);  acc[9]  = fmaf(w, f.y, acc[9]);
        f = __half22float2(*(__half2*)&a.hb.y); acc[10] = fmaf(w, f.x, acc[10]); acc[11] = fmaf(w, f.y, acc[11]);
        f = __half22float2(*(__half2*)&a.hb.z); acc[12] = fmaf(w, f.x, acc[12]); acc[13] = fmaf(w, f.y, acc[13]);
        f = __half22float2(*(__half2*)&a.hb.w); acc[14] = fmaf(w, f.x, acc[14]); acc[15] = fmaf(w, f.y, acc[15]);
        dsum += w;

        a = b; b = n; e += 4;
    }

    dsum += __shfl_xor_sync(0xffffffffu, dsum, 8);
    dsum += __shfl_xor_sync(0xffffffffu, dsum, 16);
#pragma unroll
    for (int i = 0; i < 16; i++) {
        acc[i] += __shfl_xor_sync(0xffffffffu, acc[i], 8);
        acc[i] += __shfl_xor_sync(0xffffffffu, acc[i], 16);
    }
    float inv = 1.0f / (dsum + 1e-16f);

    int c0 = 16 * j + 4 * g;
    float4 o;
    o.x = acc[4 * g + 0] * inv + bias[c0 + 0];
    o.y = acc[4 * g + 1] * inv + bias[c0 + 1];
    o.z = acc[4 * g + 2] * inv + bias[c0 + 2];
    o.w = acc[4 * g + 3] * inv + bias[c0 + 3];
    *(float4*)(outp + c0) = o;
}

__global__ void aggregate1_kernel(const float* __restrict__ bias) {
    int idx = (blockIdx.x * blockDim.x + threadIdx.x) >> 5;
    int lane = threadIdx.x & 31;
    if (idx >= g_nactive) return;
    int node = g_active[idx];
    aggregate_node(node, idx, lane, bias, (float*)g_feat4 + (size_t)node * CH);
}

__global__ void aggregate2_kernel(const float* __restrict__ bias,
                                  const int* __restrict__ roots,
                                  float* __restrict__ out) {
    int b = (blockIdx.x * blockDim.x + threadIdx.x) >> 5;
    int lane = threadIdx.x & 31;
    if (b >= N_ROOTS) return;
    int node = roots[b];
    int di = g_dense[node] - 1;
    aggregate_node(node, di, lane, bias, out + (size_t)b * CH);
}

// ---------------- launch ----------------
extern "C" void kernel_launch(void* const* d_in, const int* in_sizes, int n_in,
                              void* d_out, int out_size) {
    const float* x     = (const float*)d_in[0];
    const int*   ei    = (const int*)d_in[1];
    const int*   roots = (const int*)d_in[2];
    const float* W1    = (const float*)d_in[3];
    const float* a1s   = (const float*)d_in[4];
    const float* a1d   = (const float*)d_in[5];
    const float* b1    = (const float*)d_in[6];
    const float* W2    = (const float*)d_in[7];
    const float* a2s   = (const float*)d_in[8];
    const float* a2d   = (const float*)d_in[9];
    const float* b2    = (const float*)d_in[10];
    float*       out   = (float*)d_out;

    static cudaStream_t s2 = 0;
    static cudaEvent_t evFork = 0, evJoin = 0;
    if (s2 == 0) {
        cudaStreamCreate(&s2);
        cudaEventCreateWithFlags(&evFork, cudaEventDisableTiming);
        cudaEventCreateWithFlags(&evJoin, cudaEventDisableTiming);
        cudaFuncSetAttribute(gemm_alpha_mma,
                             cudaFuncAttributeMaxDynamicSharedMemorySize, GEMM_SMEM);
    }

    const int T = 256;
    int nb_zero  = (N_NODES / 4 + T - 1) / T;
    int nb_e8    = (N_EDGES / 8 + T - 1) / T;
    int nb_wcv   = (CH * CH + T - 1) / T;
    int nb_gemm1 = (N_NODES + GM - 1) / GM;
    int nb_gemm2 = (ACT_MAX + GM - 1) / GM;
    int nb_agg1  = (ACT_MAX * 32 + T - 1) / T;
    int nb_agg2  = (N_ROOTS * 32 + T - 1) / T;

    // side stream: W conversion + full-graph layer-1 GEMM
    cudaEventRecord(evFork, 0);
    cudaStreamWaitEvent(s2, evFork, 0);
    wconvert_kernel<<<nb_wcv, T, 0, s2>>>(W1, W2);
    gemm_alpha_mma<<<nb_gemm1, T, GEMM_SMEM, s2>>>(x, a1s, a1d, 0, 0);
    cudaEventRecord(evJoin, s2);

    // main stream: discovery + slot scatter (R11 layout)
    zero_kernel<<<nb_zero, T>>>();
    mark_roots_kernel<<<1, 64>>>(roots);
    discover_kernel<<<nb_e8, T>>>(ei);
    scatter_kernel<<<nb_e8, T>>>(ei);

    cudaStreamWaitEvent(0, evJoin, 0);
    aggregate1_kernel<<<nb_agg1, T>>>(b1);
    gemm_alpha_mma<<<nb_gemm2, T, GEMM_SMEM>>>(x, a2s, a2d, 1, 1);
    aggregate2_kernel<<<nb_agg2, T>>>(b2, roots, out);
}

// round 15
// speedup vs baseline: 1.3382x; 1.0041x over previous
#include <cuda_runtime.h>
#include <cuda_fp16.h>
#include <math.h>

#define N_NODES 50000
#define N_EDGES 1600000
#define CH 128
#define CH4 (CH / 4)
#define HEADS 4
#define NEG_SLOPE 0.2f
#define N_ROOTS 64
#define ACT_MAX 4096           // bound on |A1| (realistic ~2100); dense+1 fits in 13 bits
#define CAP 128                // slots per active node
#define NMASK ((N_NODES + 31) / 32 + 1)
#define DENSE_MASK 0x1FFFu     // low 13 bits of g_dense; 0x1FFF = claiming/overflow

#define GM 128                 // gemm rows per block
#define SX 136                 // gemm smem stride (halves)
#define GEMM_SMEM ((GM * SX + CH * SX) * 2)

// ---------------- persistent device scratch ----------------
__device__ uint4    g_hh[(size_t)N_NODES * 16];      // h as fp16 (128 halves/node)
__device__ float4   g_feat4[(size_t)N_NODES * CH4];  // layer-1 output (fp32)
__device__ float    g_as[N_NODES * HEADS];
__device__ float    g_ad[N_NODES * HEADS];
__device__ __half   g_W16[2][CH * CH];               // W1,W2 fp16, transposed (n-major)
__device__ unsigned g_rootmask[NMASK];               // 6.25 KB, L1-resident
__device__ unsigned g_actmask[NMASK];
__device__ unsigned g_dense[N_NODES];                // (ver<<13)|(dense+1); epoch-versioned, never re-zeroed
__device__ int      g_active[ACT_MAX];
__device__ int      g_cnt[ACT_MAX];
__device__ int      g_slots[(size_t)ACT_MAX * CAP];
__device__ int      g_nactive;
__device__ int      g_ver;                           // current epoch (starts 0; first call uses 1)

// ---------------- W fp16 transpose conversion (side stream) ----------------
__global__ void wconvert_kernel(const float* __restrict__ W1,
                                const float* __restrict__ W2) {
    int idx = blockIdx.x * blockDim.x + threadIdx.x;
    if (idx < CH * CH) {
        int n = idx >> 7, k = idx & 127;
        g_W16[0][idx] = __float2half(W1[k * CH + n]);
        g_W16[1][idx] = __float2half(W2[k * CH + n]);
    }
}

// ---------------- epoch-versioned claim (no per-call g_dense zeroing) ----------------
__device__ __forceinline__ void claim_active(int node, unsigned ver) {
    unsigned tag = ver << 13;
    unsigned cur = g_dense[node];
    while ((cur >> 13) != ver) {                 // not yet claimed this epoch
        unsigned old = atomicCAS(&g_dense[node], cur, tag | DENSE_MASK);
        if (old == cur) {                        // we own the claim
            int p = atomicAdd(&g_nactive, 1);
            if (p < ACT_MAX) {
                g_active[p] = node;
                g_slots[(size_t)p * CAP] = node; // self loop in slot 0
                g_cnt[p] = 1;
                atomicOr(&g_actmask[node >> 5], 1u << (node & 31));
                g_dense[node] = tag | (unsigned)(p + 1);
            }                                    // overflow: stays tag|DENSE_MASK (invalid)
            return;
        }
        cur = old;
    }
}

// ---------------- fused init + root marking (single small kernel) ----------------
__global__ void init_mark_kernel(const int* __restrict__ roots) {
    __shared__ int sver;
    int t = threadIdx.x;
    if (t == 0) {
        int v = g_ver + 1;
        if (v > 0x7FFFF) v = 1;   // 19-bit epoch, avoid 0 (initial dense state)
        g_ver = v;
        sver = v;
        g_nactive = 0;
    }
    __syncthreads();
    unsigned ver = (unsigned)sver;
    for (int i = t; i < NMASK; i += blockDim.x) { g_rootmask[i] = 0u; g_actmask[i] = 0u; }
    __syncthreads();
    if (t < N_ROOTS) {
        int r = roots[t];
        atomicOr(&g_rootmask[r >> 5], 1u << (r & 31));
        claim_active(r, ver);
    }
}

// ---------------- discover (PDL): prefetch dst before grid-dependency sync ----------------
__global__ void discover_kernel(const int* __restrict__ ei) {
    int e8 = blockIdx.x * blockDim.x + threadIdx.x;
    bool havework = (e8 < N_EDGES / 8);
    int4 d0 = make_int4(0, 0, 0, 0), d1 = make_int4(0, 0, 0, 0);
    if (havework) {
        const int4* dst4 = (const int4*)(ei + N_EDGES);
        d0 = dst4[2 * e8];
        d1 = dst4[2 * e8 + 1];
    }
    cudaGridDependencySynchronize();   // wait for init_mark (PDL launch)
    if (!havework) return;
    unsigned ver = (unsigned)g_ver;
    int dv[8] = {d0.x, d0.y, d0.z, d0.w, d1.x, d1.y, d1.z, d1.w};
#pragma unroll
    for (int k = 0; k < 8; k++) {
        int dst = dv[k];
        if ((g_rootmask[dst >> 5] >> (dst & 31)) & 1u) {
            claim_active(ei[8 * e8 + k], ver);
        }
    }
}

// ---------------- scatter (PDL): prefetch dst before grid-dependency sync ----------------
__global__ void scatter_kernel(const int* __restrict__ ei) {
    int e8 = blockIdx.x * blockDim.x + threadIdx.x;
    bool havework = (e8 < N_EDGES / 8);
    int4 d0 = make_int4(0, 0, 0, 0), d1 = make_int4(0, 0, 0, 0);
    if (havework) {
        const int4* dst4 = (const int4*)(ei + N_EDGES);
        d0 = dst4[2 * e8];
        d1 = dst4[2 * e8 + 1];
    }
    cudaGridDependencySynchronize();   // wait for discover (PDL launch)
    if (!havework) return;
    unsigned ver = (unsigned)g_ver;
    int dv[8] = {d0.x, d0.y, d0.z, d0.w, d1.x, d1.y, d1.z, d1.w};
#pragma unroll
    for (int k = 0; k < 8; k++) {
        int dst = dv[k];
        if ((g_actmask[dst >> 5] >> (dst & 31)) & 1u) {
            unsigned di = g_dense[dst];
            unsigned dn = di & DENSE_MASK;
            if ((di >> 13) == ver && dn > 0u && dn < DENSE_MASK) {
                int src = ei[8 * e8 + k];
                int pos = atomicAdd(&g_cnt[dn - 1], 1);
                if (pos < CAP) g_slots[(size_t)(dn - 1) * CAP + pos] = src;
            }
        }
    }
}

// ---------------- HMMA GEMM + fused alpha logits, fp16 h output ----------------
// use_act=0 (PDL over wconvert): stage x first, sync, then stage W.
__global__ __launch_bounds__(256) void gemm_alpha_mma(
        const float* __restrict__ Xin,
        const float* __restrict__ asrc,
        const float* __restrict__ adst,
        int widx, int use_act) {
    extern __shared__ __half smh[];
    __half* xs = smh;               // [GM][SX]
    __half* Wt = smh + GM * SX;     // [128 n][SX k]

    int tid = threadIdx.x;
    int lane = tid & 31;
    int w = tid >> 5;
    int row0 = blockIdx.x * GM;

    if (!use_act) {
        // prologue independent of wconvert: stage x while wconvert may still run
        int nact = N_NODES;
        if (row0 < nact) {
#pragma unroll
            for (int i = 0; i < 16; i++) {
                int idx = tid + 256 * i;
                int r = idx >> 5, k4 = idx & 31;
                int pos = row0 + r;
                float4 v = make_float4(0.f, 0.f, 0.f, 0.f);
                if (pos < nact) {
                    v = *(const float4*)(Xin + (size_t)pos * CH + 4 * k4);
                }
                *(__half2*)(xs + r * SX + 4 * k4)     = __floats2half2_rn(v.x, v.y);
                *(__half2*)(xs + r * SX + 4 * k4 + 2) = __floats2half2_rn(v.z, v.w);
            }
        }
        cudaGridDependencySynchronize();
        if (row0 >= nact) return;
    } else {
        cudaGridDependencySynchronize();   // non-PDL launch: returns immediately
        int nact = g_nactive;
        if (row0 >= nact) return;
#pragma unroll
        for (int i = 0; i < 16; i++) {
            int idx = tid + 256 * i;
            int r = idx >> 5, k4 = idx & 31;
            int pos = row0 + r;
            float4 v = make_float4(0.f, 0.f, 0.f, 0.f);
            if (pos < nact) {
                int node = g_active[pos];
                v = *(const float4*)((const float*)g_feat4 + (size_t)node * CH + 4 * k4);
                v.x = fmaxf(v.x, 0.f); v.y = fmaxf(v.y, 0.f);
                v.z = fmaxf(v.z, 0.f); v.w = fmaxf(v.w, 0.f);
            }
            *(__half2*)(xs + r * SX + 4 * k4)     = __floats2half2_rn(v.x, v.y);
            *(__half2*)(xs + r * SX + 4 * k4 + 2) = __floats2half2_rn(v.z, v.w);
        }
    }
    int nact = use_act ? g_nactive : N_NODES;

    // stage W: 2048 uint4 (pre-converted fp16, vectorized)
    const uint4* Wg = (const uint4*)g_W16[widx];
#pragma unroll
    for (int i = 0; i < 8; i++) {
        int idx8 = tid + 256 * i;
        int n  = idx8 >> 4;
        int k0 = (idx8 & 15) * 8;
        *(uint4*)(Wt + n * SX + k0) = Wg[idx8];
    }
    __syncthreads();

    int qr = lane >> 2;
    int qc = (lane & 3) * 2;
    int wrow = w * 16;

    float acc[16][4];
#pragma unroll
    for (int nt = 0; nt < 16; nt++) {
        acc[nt][0] = acc[nt][1] = acc[nt][2] = acc[nt][3] = 0.f;
    }

#pragma unroll
    for (int kc = 0; kc < CH; kc += 16) {
        unsigned a0 = *(const unsigned*)(xs + (wrow + qr) * SX + kc + qc);
        unsigned a1 = *(const unsigned*)(xs + (wrow + qr + 8) * SX + kc + qc);
        unsigned a2 = *(const unsigned*)(xs + (wrow + qr) * SX + kc + qc + 8);
        unsigned a3 = *(const unsigned*)(xs + (wrow + qr + 8) * SX + kc + qc + 8);
#pragma unroll
        for (int nt = 0; nt < 16; nt++) {
            int n = nt * 8 + qr;
            unsigned b0 = *(const unsigned*)(Wt + n * SX + kc + qc);
            unsigned b1 = *(const unsigned*)(Wt + n * SX + kc + qc + 8);
            asm volatile(
                "mma.sync.aligned.m16n8k16.row.col.f32.f16.f16.f32 "
                "{%0,%1,%2,%3}, {%4,%5,%6,%7}, {%8,%9}, {%0,%1,%2,%3};"
                : "+f"(acc[nt][0]), "+f"(acc[nt][1]), "+f"(acc[nt][2]), "+f"(acc[nt][3])
                : "r"(a0), "r"(a1), "r"(a2), "r"(a3), "r"(b0), "r"(b1));
        }
    }

    int pos0 = row0 + wrow + qr;
    int pos1 = pos0 + 8;
    int ok0 = pos0 < nact, ok1 = pos1 < nact;
    int gr0 = ok0 ? (use_act ? g_active[pos0] : pos0) : 0;
    int gr1 = ok1 ? (use_act ? g_active[pos1] : pos1) : 0;

    float s0[HEADS], d0[HEADS], s1[HEADS], d1[HEADS];
#pragma unroll
    for (int h = 0; h < HEADS; h++) { s0[h] = d0[h] = s1[h] = d1[h] = 0.f; }

#pragma unroll
    for (int nt = 0; nt < 16; nt++) {
        float2 a_s = *(const float2*)(asrc + nt * 8 + qc);
        float2 a_d = *(const float2*)(adst + nt * 8 + qc);
        int h = nt >> 2;
        s0[h] += acc[nt][0] * a_s.x + acc[nt][1] * a_s.y;
        d0[h] += acc[nt][0] * a_d.x + acc[nt][1] * a_d.y;
        s1[h] += acc[nt][2] * a_s.x + acc[nt][3] * a_s.y;
        d1[h] += acc[nt][2] * a_d.x + acc[nt][3] * a_d.y;
        if (ok0) {
            __half2 p = __floats2half2_rn(acc[nt][0], acc[nt][1]);
            ((unsigned*)g_hh)[(size_t)gr0 * 64 + nt * 4 + (lane & 3)] = *(unsigned*)&p;
        }
        if (ok1) {
            __half2 p = __floats2half2_rn(acc[nt][2], acc[nt][3]);
            ((unsigned*)g_hh)[(size_t)gr1 * 64 + nt * 4 + (lane & 3)] = *(unsigned*)&p;
        }
    }
#pragma unroll
    for (int h = 0; h < HEADS; h++) {
        s0[h] += __shfl_xor_sync(0xffffffffu, s0[h], 1);
        s0[h] += __shfl_xor_sync(0xffffffffu, s0[h], 2);
        d0[h] += __shfl_xor_sync(0xffffffffu, d0[h], 1);
        d0[h] += __shfl_xor_sync(0xffffffffu, d0[h], 2);
        s1[h] += __shfl_xor_sync(0xffffffffu, s1[h], 1);
        s1[h] += __shfl_xor_sync(0xffffffffu, s1[h], 2);
        d1[h] += __shfl_xor_sync(0xffffffffu, d1[h], 1);
        d1[h] += __shfl_xor_sync(0xffffffffu, d1[h], 2);
    }
    if ((lane & 3) == 0) {
#pragma unroll
        for (int h = 0; h < HEADS; h++) {
            if (ok0) { g_as[gr0 * HEADS + h] = s0[h]; g_ad[gr0 * HEADS + h] = d0[h]; }
            if (ok1) { g_as[gr1 * HEADS + h] = s1[h]; g_ad[gr1 * HEADS + h] = d1[h]; }
        }
    }
}

// ---------------- aggregation core: warp/node, depth-2 pipelined ----------------
struct EdgeState { float as; uint4 ha, hb; };

__device__ __forceinline__ void load_edge(const int* __restrict__ slots, int e,
                                          int head, int j, EdgeState& st) {
    int s = slots[e];
    st.as = g_as[s * HEADS + head];
    st.ha = g_hh[(size_t)s * 16 + 2 * j];
    st.hb = g_hh[(size_t)s * 16 + 2 * j + 1];
}

__device__ __forceinline__ void aggregate_node(int node, int di, int lane,
                                               const float* __restrict__ bias,
                                               float* __restrict__ outp) {
    int g = lane >> 3;
    int j = lane & 7;
    int head = j >> 1;

    float ad = g_ad[node * HEADS + head];
    const int* slots = g_slots + (size_t)di * CAP;
    int cnt = g_cnt[di];
    if (cnt > CAP) cnt = CAP;

    float dsum = 0.0f;
    float acc[16];
#pragma unroll
    for (int i = 0; i < 16; i++) acc[i] = 0.0f;

    EdgeState a = {}, b = {};
    int e = g;
    if (e < cnt)     load_edge(slots, e, head, j, a);
    if (e + 4 < cnt) load_edge(slots, e + 4, head, j, b);

    while (e < cnt) {
        EdgeState n = {};
        if (e + 8 < cnt) load_edge(slots, e + 8, head, j, n);

        float v = a.as + ad;
        v = fmaxf(v, NEG_SLOPE * v);
        float w = __expf(v);
        float2 f;
        f = __half22float2(*(__half2*)&a.ha.x); acc[0]  = fmaf(w, f.x, acc[0]);  acc[1]  = fmaf(w, f.y, acc[1]);
        f = __half22float2(*(__half2*)&a.ha.y); acc[2]  = fmaf(w, f.x, acc[2]);  acc[3]  = fmaf(w, f.y, acc[3]);
        f = __half22float2(*(__half2*)&a.ha.z); acc[4]  = fmaf(w, f.x, acc[4]);  acc[5]  = fmaf(w, f.y, acc[5]);
        f = __half22float2(*(__half2*)&a.ha.w); acc[6]  = fmaf(w, f.x, acc[6]);  acc[7]  = fmaf(w, f.y, acc[7]);
        f = __half22float2(*(__half2*)&a.hb.x); acc[8]  = fmaf(w, f.x, acc[8]);  acc[9]  = fmaf(w, f.y, acc[9]);
        f = __half22float2(*(__half2*)&a.hb.y); acc[10] = fmaf(w, f.x, acc[10]); acc[11] = fmaf(w, f.y, acc[11]);
        f = __half22float2(*(__half2*)&a.hb.z); acc[12] = fmaf(w, f.x, acc[12]); acc[13] = fmaf(w, f.y, acc[13]);
        f = __half22float2(*(__half2*)&a.hb.w); acc[14] = fmaf(w, f.x, acc[14]); acc[15] = fmaf(w, f.y, acc[15]);
        dsum += w;

        a = b; b = n; e += 4;
    }

    dsum += __shfl_xor_sync(0xffffffffu, dsum, 8);
    dsum += __shfl_xor_sync(0xffffffffu, dsum, 16);
#pragma unroll
    for (int i = 0; i < 16; i++) {
        acc[i] += __shfl_xor_sync(0xffffffffu, acc[i], 8);
        acc[i] += __shfl_xor_sync(0xffffffffu, acc[i], 16);
    }
    float inv = 1.0f / (dsum + 1e-16f);

    int c0 = 16 * j + 4 * g;
    float4 o;
    o.x = acc[4 * g + 0] * inv + bias[c0 + 0];
    o.y = acc[4 * g + 1] * inv + bias[c0 + 1];
    o.z = acc[4 * g + 2] * inv + bias[c0 + 2];
    o.w = acc[4 * g + 3] * inv + bias[c0 + 3];
    *(float4*)(outp + c0) = o;
}

__global__ void aggregate1_kernel(const float* __restrict__ bias) {
    int idx = (blockIdx.x * blockDim.x + threadIdx.x) >> 5;
    int lane = threadIdx.x & 31;
    if (idx >= g_nactive) return;
    int node = g_active[idx];
    aggregate_node(node, idx, lane, bias, (float*)g_feat4 + (size_t)node * CH);
}

__global__ void aggregate2_kernel(const float* __restrict__ bias,
                                  const int* __restrict__ roots,
                                  float* __restrict__ out) {
    int b = (blockIdx.x * blockDim.x + threadIdx.x) >> 5;
    int lane = threadIdx.x & 31;
    if (b >= N_ROOTS) return;
    int node = roots[b];
    int di = (int)(g_dense[node] & DENSE_MASK) - 1;
    aggregate_node(node, di, lane, bias, out + (size_t)b * CH);
}

// ---------------- launch ----------------
extern "C" void kernel_launch(void* const* d_in, const int* in_sizes, int n_in,
                              void* d_out, int out_size) {
    const float* x     = (const float*)d_in[0];
    const int*   ei    = (const int*)d_in[1];
    const int*   roots = (const int*)d_in[2];
    const float* W1    = (const float*)d_in[3];
    const float* a1s   = (const float*)d_in[4];
    const float* a1d   = (const float*)d_in[5];
    const float* b1    = (const float*)d_in[6];
    const float* W2    = (const float*)d_in[7];
    const float* a2s   = (const float*)d_in[8];
    const float* a2d   = (const float*)d_in[9];
    const float* b2    = (const float*)d_in[10];
    float*       out   = (float*)d_out;

    static cudaStream_t s2 = 0;
    static cudaEvent_t evFork = 0, evJoin = 0;
    if (s2 == 0) {
        cudaStreamCreate(&s2);
        cudaEventCreateWithFlags(&evFork, cudaEventDisableTiming);
        cudaEventCreateWithFlags(&evJoin, cudaEventDisableTiming);
        cudaFuncSetAttribute(gemm_alpha_mma,
                             cudaFuncAttributeMaxDynamicSharedMemorySize, GEMM_SMEM);
    }

    const int T = 256;
    int nb_e8    = (N_EDGES / 8 + T - 1) / T;
    int nb_wcv   = (CH * CH + T - 1) / T;
    int nb_gemm1 = (N_NODES + GM - 1) / GM;
    int nb_gemm2 = (ACT_MAX + GM - 1) / GM;
    int nb_agg1  = (ACT_MAX * 32 + T - 1) / T;
    int nb_agg2  = (N_ROOTS * 32 + T - 1) / T;

    cudaLaunchAttribute pdl[1];
    pdl[0].id = cudaLaunchAttributeProgrammaticStreamSerialization;
    pdl[0].val.programmaticStreamSerializationAllowed = 1;

    // side stream: W conversion, then gemm1 with PDL (stages x while wconvert finishes)
    cudaEventRecord(evFork, 0);
    cudaStreamWaitEvent(s2, evFork, 0);
    wconvert_kernel<<<nb_wcv, T, 0, s2>>>(W1, W2);
    {
        cudaLaunchConfig_t cfg = {};
        cfg.gridDim = dim3(nb_gemm1); cfg.blockDim = dim3(T);
        cfg.dynamicSmemBytes = GEMM_SMEM; cfg.stream = s2;
        cfg.attrs = pdl; cfg.numAttrs = 1;
        int widx = 0, uact = 0;
        cudaLaunchKernelEx(&cfg, gemm_alpha_mma, x, a1s, a1d, widx, uact);
    }
    cudaEventRecord(evJoin, s2);

    // main stream: init+mark, then PDL discover + scatter (dst prefetch overlap)
    init_mark_kernel<<<1, 1024>>>(roots);
    {
        cudaLaunchConfig_t cfg = {};
        cfg.gridDim = dim3(nb_e8); cfg.blockDim = dim3(T);
        cfg.stream = 0; cfg.attrs = pdl; cfg.numAttrs = 1;
        cudaLaunchKernelEx(&cfg, discover_kernel, ei);
        cudaLaunchKernelEx(&cfg, scatter_kernel, ei);
    }

    cudaStreamWaitEvent(0, evJoin, 0);
    aggregate1_kernel<<<nb_agg1, T>>>(b1);
    gemm_alpha_mma<<<nb_gemm2, T, GEMM_SMEM>>>(x, a2s, a2d, 1, 1);
    aggregate2_kernel<<<nb_agg2, T>>>(b2, roots, out);
}

// round 16
// speedup vs baseline: 1.3406x; 1.0018x over previous
#include <cuda_runtime.h>
#include <cuda_fp16.h>
#include <math.h>

#define N_NODES 50000
#define N_EDGES 1600000
#define CH 128
#define CH4 (CH / 4)
#define HEADS 4
#define NEG_SLOPE 0.2f
#define N_ROOTS 64
#define ACT_MAX 4096           // bound on |A1| (realistic ~2100); dense+1 fits in 13 bits
#define CAP 128                // slots per active node
#define NMASK ((N_NODES + 31) / 32 + 1)
#define DENSE_MASK 0x1FFFu

#define GM 128                 // gemm rows per block
#define SX 136                 // gemm smem stride (halves)
#define GEMM_SMEM ((GM * SX + CH * SX) * 2)

// ---------------- persistent device scratch ----------------
__device__ uint4    g_hh[(size_t)N_NODES * 16];      // h as fp16 (128 halves/node)
__device__ float4   g_feat4[(size_t)N_NODES * CH4];  // layer-1 output (fp32)
__device__ float    g_as[N_NODES * HEADS];
__device__ float    g_ad[N_NODES * HEADS];
__device__ __half   g_W16[2][CH * CH];               // W1,W2 fp16, transposed (n-major)
__device__ unsigned g_rootmask[NMASK];               // 6.25 KB
__device__ unsigned g_actmask[NMASK];
__device__ unsigned g_dense[N_NODES];                // (ver<<13)|(dense+1); epoch-versioned
__device__ int      g_active[ACT_MAX];
__device__ int      g_cnt[ACT_MAX];
__device__ int      g_slots[(size_t)ACT_MAX * CAP];
__device__ int      g_nactive;
__device__ int      g_ver;

// ---------------- W fp16 transpose conversion (side stream) ----------------
__global__ void wconvert_kernel(const float* __restrict__ W1,
                                const float* __restrict__ W2) {
    int idx = blockIdx.x * blockDim.x + threadIdx.x;
    if (idx < CH * CH) {
        int n = idx >> 7, k = idx & 127;
        g_W16[0][idx] = __float2half(W1[k * CH + n]);
        g_W16[1][idx] = __float2half(W2[k * CH + n]);
    }
}

// ---------------- epoch-versioned claim ----------------
__device__ __forceinline__ void claim_active(int node, unsigned ver) {
    unsigned tag = ver << 13;
    unsigned cur = g_dense[node];
    while ((cur >> 13) != ver) {
        unsigned old = atomicCAS(&g_dense[node], cur, tag | DENSE_MASK);
        if (old == cur) {
            int p = atomicAdd(&g_nactive, 1);
            if (p < ACT_MAX) {
                g_active[p] = node;
                g_slots[(size_t)p * CAP] = node;   // self loop in slot 0
                g_cnt[p] = 1;
                atomicOr(&g_actmask[node >> 5], 1u << (node & 31));
                g_dense[node] = tag | (unsigned)(p + 1);
            }
            return;
        }
        cur = old;
    }
}

// ---------------- fused init + root marking ----------------
__global__ void init_mark_kernel(const int* __restrict__ roots) {
    __shared__ int sver;
    int t = threadIdx.x;
    if (t == 0) {
        int v = g_ver + 1;
        if (v > 0x7FFFF) v = 1;
        g_ver = v;
        sver = v;
        g_nactive = 0;
    }
    __syncthreads();
    unsigned ver = (unsigned)sver;
    for (int i = t; i < NMASK; i += blockDim.x) { g_rootmask[i] = 0u; g_actmask[i] = 0u; }
    __syncthreads();
    if (t < N_ROOTS) {
        int r = roots[t];
        atomicOr(&g_rootmask[r >> 5], 1u << (r & 31));
        claim_active(r, ver);
    }
}

// ---------------- discover (PDL, dst prefetch) ----------------
__global__ void discover_kernel(const int* __restrict__ ei) {
    int e8 = blockIdx.x * blockDim.x + threadIdx.x;
    bool havework = (e8 < N_EDGES / 8);
    int4 d0 = make_int4(0, 0, 0, 0), d1 = make_int4(0, 0, 0, 0);
    if (havework) {
        const int4* dst4 = (const int4*)(ei + N_EDGES);
        d0 = dst4[2 * e8];
        d1 = dst4[2 * e8 + 1];
    }
    cudaGridDependencySynchronize();
    if (!havework) return;
    unsigned ver = (unsigned)g_ver;
    int dv[8] = {d0.x, d0.y, d0.z, d0.w, d1.x, d1.y, d1.z, d1.w};
#pragma unroll
    for (int k = 0; k < 8; k++) {
        int dst = dv[k];
        if ((__ldg(&g_rootmask[dst >> 5]) >> (dst & 31)) & 1u) {
            claim_active(ei[8 * e8 + k], ver);
        }
    }
}

// ---------------- scatter (PDL, dst prefetch) ----------------
__global__ void scatter_kernel(const int* __restrict__ ei) {
    int e8 = blockIdx.x * blockDim.x + threadIdx.x;
    bool havework = (e8 < N_EDGES / 8);
    int4 d0 = make_int4(0, 0, 0, 0), d1 = make_int4(0, 0, 0, 0);
    if (havework) {
        const int4* dst4 = (const int4*)(ei + N_EDGES);
        d0 = dst4[2 * e8];
        d1 = dst4[2 * e8 + 1];
    }
    cudaGridDependencySynchronize();
    if (!havework) return;
    unsigned ver = (unsigned)g_ver;
    int dv[8] = {d0.x, d0.y, d0.z, d0.w, d1.x, d1.y, d1.z, d1.w};
#pragma unroll
    for (int k = 0; k < 8; k++) {
        int dst = dv[k];
        if ((__ldg(&g_actmask[dst >> 5]) >> (dst & 31)) & 1u) {
            unsigned di = g_dense[dst];
            unsigned dn = di & DENSE_MASK;
            if ((di >> 13) == ver && dn > 0u && dn < DENSE_MASK) {
                int src = ei[8 * e8 + k];
                int pos = atomicAdd(&g_cnt[dn - 1], 1);
                if (pos < CAP) g_slots[(size_t)(dn - 1) * CAP + pos] = src;
            }
        }
    }
}

// ---------------- HMMA GEMM + fused alpha logits, fp16 h output ----------------
__global__ __launch_bounds__(256) void gemm_alpha_mma(
        const float* __restrict__ Xin,
        const float* __restrict__ asrc,
        const float* __restrict__ adst,
        int widx, int use_act) {
    extern __shared__ __half smh[];
    __half* xs = smh;               // [GM][SX]
    __half* Wt = smh + GM * SX;     // [128 n][SX k]

    int tid = threadIdx.x;
    int lane = tid & 31;
    int w = tid >> 5;
    int row0 = blockIdx.x * GM;

    if (!use_act) {
        int nact = N_NODES;
        if (row0 < nact) {
#pragma unroll
            for (int i = 0; i < 16; i++) {
                int idx = tid + 256 * i;
                int r = idx >> 5, k4 = idx & 31;
                int pos = row0 + r;
                float4 v = make_float4(0.f, 0.f, 0.f, 0.f);
                if (pos < nact) {
                    v = *(const float4*)(Xin + (size_t)pos * CH + 4 * k4);
                }
                *(__half2*)(xs + r * SX + 4 * k4)     = __floats2half2_rn(v.x, v.y);
                *(__half2*)(xs + r * SX + 4 * k4 + 2) = __floats2half2_rn(v.z, v.w);
            }
        }
        cudaGridDependencySynchronize();
        if (row0 >= nact) return;
    } else {
        cudaGridDependencySynchronize();
        int nact = g_nactive;
        if (row0 >= nact) return;
#pragma unroll
        for (int i = 0; i < 16; i++) {
            int idx = tid + 256 * i;
            int r = idx >> 5, k4 = idx & 31;
            int pos = row0 + r;
            float4 v = make_float4(0.f, 0.f, 0.f, 0.f);
            if (pos < nact) {
                int node = g_active[pos];
                v = *(const float4*)((const float*)g_feat4 + (size_t)node * CH + 4 * k4);
                v.x = fmaxf(v.x, 0.f); v.y = fmaxf(v.y, 0.f);
                v.z = fmaxf(v.z, 0.f); v.w = fmaxf(v.w, 0.f);
            }
            *(__half2*)(xs + r * SX + 4 * k4)     = __floats2half2_rn(v.x, v.y);
            *(__half2*)(xs + r * SX + 4 * k4 + 2) = __floats2half2_rn(v.z, v.w);
        }
    }
    int nact = use_act ? g_nactive : N_NODES;

    const uint4* Wg = (const uint4*)g_W16[widx];
#pragma unroll
    for (int i = 0; i < 8; i++) {
        int idx8 = tid + 256 * i;
        int n  = idx8 >> 4;
        int k0 = (idx8 & 15) * 8;
        *(uint4*)(Wt + n * SX + k0) = Wg[idx8];
    }
    __syncthreads();

    int qr = lane >> 2;
    int qc = (lane & 3) * 2;
    int wrow = w * 16;

    float acc[16][4];
#pragma unroll
    for (int nt = 0; nt < 16; nt++) {
        acc[nt][0] = acc[nt][1] = acc[nt][2] = acc[nt][3] = 0.f;
    }

#pragma unroll
    for (int kc = 0; kc < CH; kc += 16) {
        unsigned a0 = *(const unsigned*)(xs + (wrow + qr) * SX + kc + qc);
        unsigned a1 = *(const unsigned*)(xs + (wrow + qr + 8) * SX + kc + qc);
        unsigned a2 = *(const unsigned*)(xs + (wrow + qr) * SX + kc + qc + 8);
        unsigned a3 = *(const unsigned*)(xs + (wrow + qr + 8) * SX + kc + qc + 8);
#pragma unroll
        for (int nt = 0; nt < 16; nt++) {
            int n = nt * 8 + qr;
            unsigned b0 = *(const unsigned*)(Wt + n * SX + kc + qc);
            unsigned b1 = *(const unsigned*)(Wt + n * SX + kc + qc + 8);
            asm volatile(
                "mma.sync.aligned.m16n8k16.row.col.f32.f16.f16.f32 "
                "{%0,%1,%2,%3}, {%4,%5,%6,%7}, {%8,%9}, {%0,%1,%2,%3};"
                : "+f"(acc[nt][0]), "+f"(acc[nt][1]), "+f"(acc[nt][2]), "+f"(acc[nt][3])
                : "r"(a0), "r"(a1), "r"(a2), "r"(a3), "r"(b0), "r"(b1));
        }
    }

    int pos0 = row0 + wrow + qr;
    int pos1 = pos0 + 8;
    int ok0 = pos0 < nact, ok1 = pos1 < nact;
    int gr0 = ok0 ? (use_act ? g_active[pos0] : pos0) : 0;
    int gr1 = ok1 ? (use_act ? g_active[pos1] : pos1) : 0;

    float s0[HEADS], d0[HEADS], s1[HEADS], d1[HEADS];
#pragma unroll
    for (int h = 0; h < HEADS; h++) { s0[h] = d0[h] = s1[h] = d1[h] = 0.f; }

#pragma unroll
    for (int nt = 0; nt < 16; nt++) {
        float2 a_s = *(const float2*)(asrc + nt * 8 + qc);
        float2 a_d = *(const float2*)(adst + nt * 8 + qc);
        int h = nt >> 2;
        s0[h] += acc[nt][0] * a_s.x + acc[nt][1] * a_s.y;
        d0[h] += acc[nt][0] * a_d.x + acc[nt][1] * a_d.y;
        s1[h] += acc[nt][2] * a_s.x + acc[nt][3] * a_s.y;
        d1[h] += acc[nt][2] * a_d.x + acc[nt][3] * a_d.y;
        if (ok0) {
            __half2 p = __floats2half2_rn(acc[nt][0], acc[nt][1]);
            ((unsigned*)g_hh)[(size_t)gr0 * 64 + nt * 4 + (lane & 3)] = *(unsigned*)&p;
        }
        if (ok1) {
            __half2 p = __floats2half2_rn(acc[nt][2], acc[nt][3]);
            ((unsigned*)g_hh)[(size_t)gr1 * 64 + nt * 4 + (lane & 3)] = *(unsigned*)&p;
        }
    }
#pragma unroll
    for (int h = 0; h < HEADS; h++) {
        s0[h] += __shfl_xor_sync(0xffffffffu, s0[h], 1);
        s0[h] += __shfl_xor_sync(0xffffffffu, s0[h], 2);
        d0[h] += __shfl_xor_sync(0xffffffffu, d0[h], 1);
        d0[h] += __shfl_xor_sync(0xffffffffu, d0[h], 2);
        s1[h] += __shfl_xor_sync(0xffffffffu, s1[h], 1);
        s1[h] += __shfl_xor_sync(0xffffffffu, s1[h], 2);
        d1[h] += __shfl_xor_sync(0xffffffffu, d1[h], 1);
        d1[h] += __shfl_xor_sync(0xffffffffu, d1[h], 2);
    }
    if ((lane & 3) == 0) {
#pragma unroll
        for (int h = 0; h < HEADS; h++) {
            if (ok0) { g_as[gr0 * HEADS + h] = s0[h]; g_ad[gr0 * HEADS + h] = d0[h]; }
            if (ok1) { g_as[gr1 * HEADS + h] = s1[h]; g_ad[gr1 * HEADS + h] = d1[h]; }
        }
    }
}

// ---------------- aggregation core: warp/node, depth-2 pipelined ----------------
struct EdgeState { float as; uint4 ha, hb; };

__device__ __forceinline__ void load_edge(const int* __restrict__ slots, int e,
                                          int head, int j, EdgeState& st) {
    int s = slots[e];
    st.as = g_as[s * HEADS + head];
    st.ha = g_hh[(size_t)s * 16 + 2 * j];
    st.hb = g_hh[(size_t)s * 16 + 2 * j + 1];
}

__device__ __forceinline__ void aggregate_node(int node, int di, int lane,
                                               const float* __restrict__ bias,
                                               float* __restrict__ outp) {
    int g = lane >> 3;
    int j = lane & 7;
    int head = j >> 1;

    float ad = g_ad[node * HEADS + head];
    const int* slots = g_slots + (size_t)di * CAP;
    int cnt = g_cnt[di];
    if (cnt > CAP) cnt = CAP;

    float dsum = 0.0f;
    float acc[16];
#pragma unroll
    for (int i = 0; i < 16; i++) acc[i] = 0.0f;

    EdgeState a = {}, b = {};
    int e = g;
    if (e < cnt)     load_edge(slots, e, head, j, a);
    if (e + 4 < cnt) load_edge(slots, e + 4, head, j, b);

    while (e < cnt) {
        EdgeState n = {};
        if (e + 8 < cnt) load_edge(slots, e + 8, head, j, n);

        float v = a.as + ad;
        v = fmaxf(v, NEG_SLOPE * v);
        float w = __expf(v);
        float2 f;
        f = __half22float2(*(__half2*)&a.ha.x); acc[0]  = fmaf(w, f.x, acc[0]);  acc[1]  = fmaf(w, f.y, acc[1]);
        f = __half22float2(*(__half2*)&a.ha.y); acc[2]  = fmaf(w, f.x, acc[2]);  acc[3]  = fmaf(w, f.y, acc[3]);
        f = __half22float2(*(__half2*)&a.ha.z); acc[4]  = fmaf(w, f.x, acc[4]);  acc[5]  = fmaf(w, f.y, acc[5]);
        f = __half22float2(*(__half2*)&a.ha.w); acc[6]  = fmaf(w, f.x, acc[6]);  acc[7]  = fmaf(w, f.y, acc[7]);
        f = __half22float2(*(__half2*)&a.hb.x); acc[8]  = fmaf(w, f.x, acc[8]);  acc[9]  = fmaf(w, f.y, acc[9]);
        f = __half22float2(*(__half2*)&a.hb.y); acc[10] = fmaf(w, f.x, acc[10]); acc[11] = fmaf(w, f.y, acc[11]);
        f = __half22float2(*(__half2*)&a.hb.z); acc[12] = fmaf(w, f.x, acc[12]); acc[13] = fmaf(w, f.y, acc[13]);
        f = __half22float2(*(__half2*)&a.hb.w); acc[14] = fmaf(w, f.x, acc[14]); acc[15] = fmaf(w, f.y, acc[15]);
        dsum += w;

        a = b; b = n; e += 4;
    }

    dsum += __shfl_xor_sync(0xffffffffu, dsum, 8);
    dsum += __shfl_xor_sync(0xffffffffu, dsum, 16);
#pragma unroll
    for (int i = 0; i < 16; i++) {
        acc[i] += __shfl_xor_sync(0xffffffffu, acc[i], 8);
        acc[i] += __shfl_xor_sync(0xffffffffu, acc[i], 16);
    }
    float inv = 1.0f / (dsum + 1e-16f);

    int c0 = 16 * j + 4 * g;
    float4 o;
    o.x = acc[4 * g + 0] * inv + bias[c0 + 0];
    o.y = acc[4 * g + 1] * inv + bias[c0 + 1];
    o.z = acc[4 * g + 2] * inv + bias[c0 + 2];
    o.w = acc[4 * g + 3] * inv + bias[c0 + 3];
    *(float4*)(outp + c0) = o;
}

__global__ void aggregate1_kernel(const float* __restrict__ bias) {
    cudaGridDependencySynchronize();   // no-op when launched normally
    int idx = (blockIdx.x * blockDim.x + threadIdx.x) >> 5;
    int lane = threadIdx.x & 31;
    if (idx >= g_nactive) return;
    int node = g_active[idx];
    aggregate_node(node, idx, lane, bias, (float*)g_feat4 + (size_t)node * CH);
}

__global__ void aggregate2_kernel(const float* __restrict__ bias,
                                  const int* __restrict__ roots,
                                  float* __restrict__ out) {
    cudaGridDependencySynchronize();   // PDL: wait for gemm2 state
    int b = (blockIdx.x * blockDim.x + threadIdx.x) >> 5;
    int lane = threadIdx.x & 31;
    if (b >= N_ROOTS) return;
    int node = roots[b];
    int di = (int)(g_dense[node] & DENSE_MASK) - 1;
    aggregate_node(node, di, lane, bias, out + (size_t)b * CH);
}

// ---------------- launch ----------------
extern "C" void kernel_launch(void* const* d_in, const int* in_sizes, int n_in,
                              void* d_out, int out_size) {
    const float* x     = (const float*)d_in[0];
    const int*   ei    = (const int*)d_in[1];
    const int*   roots = (const int*)d_in[2];
    const float* W1    = (const float*)d_in[3];
    const float* a1s   = (const float*)d_in[4];
    const float* a1d   = (const float*)d_in[5];
    const float* b1    = (const float*)d_in[6];
    const float* W2    = (const float*)d_in[7];
    const float* a2s   = (const float*)d_in[8];
    const float* a2d   = (const float*)d_in[9];
    const float* b2    = (const float*)d_in[10];
    float*       out   = (float*)d_out;

    static cudaStream_t s2 = 0;
    static cudaEvent_t evFork = 0, evJoin = 0;
    if (s2 == 0) {
        cudaStreamCreate(&s2);
        cudaEventCreateWithFlags(&evFork, cudaEventDisableTiming);
        cudaEventCreateWithFlags(&evJoin, cudaEventDisableTiming);
        cudaFuncSetAttribute(gemm_alpha_mma,
                             cudaFuncAttributeMaxDynamicSharedMemorySize, GEMM_SMEM);
    }

    const int T = 256;
    const int TS = 512;                               // sweep blocks
    int nb_e8    = (N_EDGES / 8 + TS - 1) / TS;
    int nb_wcv   = (CH * CH + T - 1) / T;
    int nb_gemm1 = (N_NODES + GM - 1) / GM;
    int nb_gemm2 = (ACT_MAX + GM - 1) / GM;
    int nb_agg1  = (ACT_MAX * 32 + T - 1) / T;
    int nb_agg2  = (N_ROOTS * 32 + T - 1) / T;

    cudaLaunchAttribute pdl[1];
    pdl[0].id = cudaLaunchAttributeProgrammaticStreamSerialization;
    pdl[0].val.programmaticStreamSerializationAllowed = 1;

    // side stream: W conversion, then gemm1 with PDL
    cudaEventRecord(evFork, 0);
    cudaStreamWaitEvent(s2, evFork, 0);
    wconvert_kernel<<<nb_wcv, T, 0, s2>>>(W1, W2);
    {
        cudaLaunchConfig_t cfg = {};
        cfg.gridDim = dim3(nb_gemm1); cfg.blockDim = dim3(T);
        cfg.dynamicSmemBytes = GEMM_SMEM; cfg.stream = s2;
        cfg.attrs = pdl; cfg.numAttrs = 1;
        int widx = 0, uact = 0;
        cudaLaunchKernelEx(&cfg, gemm_alpha_mma, x, a1s, a1d, widx, uact);
    }
    cudaEventRecord(evJoin, s2);

    // main stream: init+mark, PDL discover + scatter
    init_mark_kernel<<<1, 1024>>>(roots);
    {
        cudaLaunchConfig_t cfg = {};
        cfg.gridDim = dim3(nb_e8); cfg.blockDim = dim3(TS);
        cfg.stream = 0; cfg.attrs = pdl; cfg.numAttrs = 1;
        cudaLaunchKernelEx(&cfg, discover_kernel, ei);
        cudaLaunchKernelEx(&cfg, scatter_kernel, ei);
    }

    // tail: agg1 (after cross-stream join), then PDL gemm2, PDL agg2
    cudaStreamWaitEvent(0, evJoin, 0);
    aggregate1_kernel<<<nb_agg1, T>>>(b1);
    {
        cudaLaunchConfig_t cfg = {};
        cfg.gridDim = dim3(nb_gemm2); cfg.blockDim = dim3(T);
        cfg.dynamicSmemBytes = GEMM_SMEM; cfg.stream = 0;
        cfg.attrs = pdl; cfg.numAttrs = 1;
        int widx = 1, uact = 1;
        cudaLaunchKernelEx(&cfg, gemm_alpha_mma, x, a2s, a2d, widx, uact);
    }
    {
        cudaLaunchConfig_t cfg = {};
        cfg.gridDim = dim3(nb_agg2); cfg.blockDim = dim3(T);
        cfg.stream = 0; cfg.attrs = pdl; cfg.numAttrs = 1;
        cudaLaunchKernelEx(&cfg, aggregate2_kernel, b2, roots, out);
    }
}